// round 2
// baseline (speedup 1.0000x reference)
#include <cuda_runtime.h>
#include <math.h>

#define N_ENT 100000
#define N_REL 64
#define E_DIM 64
#define KNB   32
#define BSZ   1024

// Scratch (no allocation allowed — device globals)
__device__ float d_Enorm[(size_t)N_ENT * E_DIM];   // normalized entity table (25.6 MB, L2-resident)
__device__ float d_RW[N_REL * E_DIM];              // RW[rel][f] = sum_e Rnorm[rel][e] * w1r[f][e]
__device__ float d_hsum[BSZ * E_DIM];              // per-root sum of hop-1 normalized neighbors

__device__ __forceinline__ float leaky(float x) { return x >= 0.f ? x : 0.2f * x; }

// ---------------------------------------------------------------------------
// K0a: normalize all entity rows into d_Enorm. 1 warp per row.
// ---------------------------------------------------------------------------
__global__ void normE_kernel(const float* __restrict__ E) {
    int warp = (blockIdx.x * blockDim.x + threadIdx.x) >> 5;
    int lane = threadIdx.x & 31;
    if (warp >= N_ENT) return;
    const float2* row = (const float2*)(E + (size_t)warp * E_DIM);
    float2 v = row[lane];
    float ss = v.x * v.x + v.y * v.y;
    #pragma unroll
    for (int o = 16; o > 0; o >>= 1) ss += __shfl_xor_sync(0xffffffffu, ss, o);
    float n = sqrtf(ss);
    float sc = (n > 1.0f) ? 1.0f / (n + 1e-7f) : 1.0f;
    float2* orow = (float2*)(d_Enorm + (size_t)warp * E_DIM);
    orow[lane] = make_float2(v.x * sc, v.y * sc);
}

// ---------------------------------------------------------------------------
// K0b: normalize R, compute RW[rel][f] = sum_e Rnorm[rel][e] * att_w1[f][64+e]
// 1 block, 64 threads.
// ---------------------------------------------------------------------------
__global__ void prepRW_kernel(const float* __restrict__ R, const float* __restrict__ w1) {
    __shared__ float Rn[N_REL][E_DIM];
    int tid = threadIdx.x;  // 64
    // thread = relation row
    {
        float ss = 0.f;
        float tmp[E_DIM];
        #pragma unroll
        for (int e = 0; e < E_DIM; e++) { float x = R[tid * E_DIM + e]; tmp[e] = x; ss += x * x; }
        float n = sqrtf(ss);
        float sc = (n > 1.0f) ? 1.0f / (n + 1e-7f) : 1.0f;
        #pragma unroll
        for (int e = 0; e < E_DIM; e++) Rn[tid][e] = tmp[e] * sc;
    }
    __syncthreads();
    // thread = f ; loop rels
    int f = tid;
    for (int rel = 0; rel < N_REL; rel++) {
        float s = 0.f;
        #pragma unroll
        for (int e = 0; e < E_DIM; e++) s += Rn[rel][e] * w1[f * 128 + 64 + e];
        d_RW[rel * E_DIM + f] = s;
    }
}

// ---------------------------------------------------------------------------
// K1: hop-1. One block (64 threads) per root.
// ---------------------------------------------------------------------------
__global__ void hop1_kernel(const int* __restrict__ entity_idx,
                            const int* __restrict__ adj_e,
                            const int* __restrict__ adj_r,
                            const float* __restrict__ w1,
                            const float* __restrict__ w2,
                            const float* __restrict__ w3,
                            const float* __restrict__ wxw,
                            const float* __restrict__ wxb,
                            const float* __restrict__ wcw,
                            const float* __restrict__ wcb,
                            float* __restrict__ out) {
    int b = blockIdx.x;
    int tid = threadIdx.x;  // 64
    __shared__ float h[E_DIM], hW[E_DIM], hid1[E_DIM], aArr[KNB], eaArr[KNB];
    __shared__ float agg[E_DIM], v1[E_DIM], red[2];
    __shared__ float t1[KNB * E_DIM];
    __shared__ int ent1[KNB], rel1[KNB];

    int eidx = entity_idx[b];
    if (tid < KNB) {
        ent1[tid] = adj_e[eidx * KNB + tid];
        rel1[tid] = adj_r[eidx * KNB + tid];
    }
    h[tid] = d_Enorm[(size_t)eidx * E_DIM + tid];
    __syncthreads();
    for (int i = tid; i < KNB * E_DIM; i += 64) {
        int n = i >> 6, e = i & 63;
        t1[i] = d_Enorm[(size_t)ent1[n] * E_DIM + e];
    }
    __syncthreads();
    // hsum (thread = dim e)
    {
        float s = 0.f;
        #pragma unroll
        for (int n = 0; n < KNB; n++) s += t1[n * E_DIM + tid];
        d_hsum[b * E_DIM + tid] = s;
    }
    // hW[f] = sum_e h[e] * w1h[f][e]
    {
        float s = 0.f;
        #pragma unroll
        for (int e = 0; e < E_DIM; e++) s += h[e] * w1[tid * 128 + e];
        hW[tid] = s;
    }
    __syncthreads();
    // attention score per neighbor
    for (int n = 0; n < KNB; n++) {
        int rel = rel1[n];
        float x = hW[tid] + d_RW[rel * E_DIM + tid];
        hid1[tid] = x > 0.f ? x : 0.f;
        __syncthreads();
        float g = 0.f;
        #pragma unroll
        for (int f = 0; f < E_DIM; f++) g += w2[tid * E_DIM + f] * hid1[f];
        g = g > 0.f ? g : 0.f;
        float c = w3[tid] * g;
        #pragma unroll
        for (int o = 16; o > 0; o >>= 1) c += __shfl_down_sync(0xffffffffu, c, o);
        if ((tid & 31) == 0) red[tid >> 5] = c;
        __syncthreads();
        if (tid == 0) {
            float aa = red[0] + red[1];
            aArr[n] = 1.f / (1.f + expf(-aa));
        }
        __syncthreads();
    }
    if (tid < KNB) eaArr[tid] = expf(aArr[tid]);
    __syncthreads();
    float S = 0.f;
    #pragma unroll
    for (int n = 0; n < KNB; n++) S += eaArr[n];
    float ag = 0.f;
    #pragma unroll
    for (int n = 0; n < KNB; n++) ag += eaArr[n] * t1[n * E_DIM + tid];
    agg[tid] = ag / S;
    __syncthreads();
    {
        float v = wxb[tid];
        #pragma unroll
        for (int e = 0; e < E_DIM; e++) v += wxw[tid * E_DIM + e] * agg[e];
        v1[tid] = leaky(v);
    }
    __syncthreads();
    {
        float em = wcb[tid];
        #pragma unroll
        for (int e = 0; e < E_DIM; e++) em += wcw[tid * 128 + e] * h[e];
        #pragma unroll
        for (int e = 0; e < E_DIM; e++) em += wcw[tid * 128 + 64 + e] * v1[e];
        em = leaky(em);
        out[b * 192 + 64 + tid] = em;
        out[b * 192 + 128 + tid] = h[tid];
    }
}

// ---------------------------------------------------------------------------
// K2: hop-2. One block (256 threads) per root. Attention factored through the
// 64-entry relation table; single-pass softmax (sigmoid output bounded).
// ---------------------------------------------------------------------------
__global__ void __launch_bounds__(256) hop2_kernel(
        const int* __restrict__ entity_idx,
        const int* __restrict__ adj_e,
        const int* __restrict__ adj_r,
        const float* __restrict__ w1,
        const float* __restrict__ w2,
        const float* __restrict__ w3,
        const float* __restrict__ wxw,
        const float* __restrict__ wxb,
        const float* __restrict__ wcw,
        const float* __restrict__ wcb,
        float* __restrict__ out) {
    int b = blockIdx.x;
    int tid = threadIdx.x;  // 256
    __shared__ float W2s[E_DIM * E_DIM];           // 16 KB
    __shared__ float hsumS[E_DIM], hW[E_DIM], eaT[N_REL], accS[E_DIM];
    __shared__ float v2[E_DIM], aggS[E_DIM];
    __shared__ int ent1s[KNB];
    __shared__ int idx2[KNB * KNB];                // 4 KB
    __shared__ unsigned char rel2[KNB * KNB];      // 1 KB
    __shared__ float hid1w[8][E_DIM];              // per-warp scratch
    __shared__ float sRed;

    int eidx = entity_idx[b];
    if (tid < KNB) ent1s[tid] = adj_e[eidx * KNB + tid];
    if (tid < E_DIM) { hsumS[tid] = d_hsum[b * E_DIM + tid]; accS[tid] = 0.f; }
    if (tid == 0) sRed = 0.f;
    for (int i = tid; i < E_DIM * E_DIM; i += 256) W2s[i] = w2[i];
    __syncthreads();
    if (tid < E_DIM) {
        float s = 0.f;
        #pragma unroll
        for (int e = 0; e < E_DIM; e++) s += hsumS[e] * w1[tid * 128 + e];
        hW[tid] = s;
    }
    __syncthreads();

    int w = tid >> 5, lane = tid & 31;
    // relation score table: 8 rels per warp
    #pragma unroll
    for (int j = 0; j < 8; j++) {
        int rel = w + j * 8;
        float x0 = hW[lane]      + d_RW[rel * E_DIM + lane];
        float x1 = hW[lane + 32] + d_RW[rel * E_DIM + lane + 32];
        hid1w[w][lane]      = x0 > 0.f ? x0 : 0.f;
        hid1w[w][lane + 32] = x1 > 0.f ? x1 : 0.f;
        __syncwarp();
        float g0 = 0.f, g1 = 0.f;
        #pragma unroll
        for (int f = 0; f < E_DIM; f++) {
            float hv = hid1w[w][f];
            g0 += W2s[lane * E_DIM + f] * hv;
            g1 += W2s[(lane + 32) * E_DIM + f] * hv;
        }
        g0 = g0 > 0.f ? g0 : 0.f;
        g1 = g1 > 0.f ? g1 : 0.f;
        float c = w3[lane] * g0 + w3[lane + 32] * g1;
        #pragma unroll
        for (int o = 16; o > 0; o >>= 1) c += __shfl_down_sync(0xffffffffu, c, o);
        if (lane == 0) {
            float aa = 1.f / (1.f + expf(-c));
            eaT[rel] = expf(aa);
        }
        __syncwarp();
    }

    // stage hop-2 indices
    for (int i = tid; i < KNB * KNB; i += 256) {
        int e1 = ent1s[i >> 5];
        idx2[i] = adj_e[e1 * KNB + (i & 31)];
        rel2[i] = (unsigned char)adj_r[e1 * KNB + (i & 31)];
    }
    __syncthreads();

    // weighted gather: each warp takes 128 neighbors, half-warp per row (float4)
    const float4* E4 = (const float4*)d_Enorm;
    int hw2 = lane >> 4, li = lane & 15;
    float4 acc = make_float4(0.f, 0.f, 0.f, 0.f);
    float sP = 0.f;
    int nbeg = w * 128;
    #pragma unroll 4
    for (int base = 0; base < 128; base += 2) {
        int n = nbeg + base + hw2;
        int idx = idx2[n];
        float ea = eaT[rel2[n]];
        float4 v = __ldg(&E4[(size_t)idx * 16 + li]);
        acc.x += ea * v.x; acc.y += ea * v.y; acc.z += ea * v.z; acc.w += ea * v.w;
        if (li == 0) sP += ea;
    }
    atomicAdd(&accS[li * 4 + 0], acc.x);
    atomicAdd(&accS[li * 4 + 1], acc.y);
    atomicAdd(&accS[li * 4 + 2], acc.z);
    atomicAdd(&accS[li * 4 + 3], acc.w);
    #pragma unroll
    for (int o = 16; o > 0; o >>= 1) sP += __shfl_down_sync(0xffffffffu, sP, o);
    if (lane == 0) atomicAdd(&sRed, sP);
    __syncthreads();

    float S = sRed;
    if (tid < E_DIM) aggS[tid] = accS[tid] / S;
    __syncthreads();
    if (tid < E_DIM) {
        float v = wxb[tid];
        #pragma unroll
        for (int e = 0; e < E_DIM; e++) v += wxw[tid * E_DIM + e] * aggS[e];
        v2[tid] = leaky(v);
    }
    __syncthreads();
    if (tid < E_DIM) {
        float em = wcb[tid];
        #pragma unroll
        for (int e = 0; e < E_DIM; e++) em += wcw[tid * 128 + e] * hsumS[e];
        #pragma unroll
        for (int e = 0; e < E_DIM; e++) em += wcw[tid * 128 + 64 + e] * v2[e];
        out[b * 192 + tid] = leaky(em);
    }
}

// ---------------------------------------------------------------------------
extern "C" void kernel_launch(void* const* d_in, const int* in_sizes, int n_in,
                              void* d_out, int out_size) {
    const int*   entity_idx = (const int*)d_in[0];
    const int*   adj_e      = (const int*)d_in[1];
    const int*   adj_r      = (const int*)d_in[2];
    const float* E          = (const float*)d_in[3];
    const float* R          = (const float*)d_in[4];
    const float* w1         = (const float*)d_in[5];
    const float* w2         = (const float*)d_in[6];
    const float* w3         = (const float*)d_in[7];
    const float* wxw        = (const float*)d_in[8];
    const float* wxb        = (const float*)d_in[9];
    const float* wcw        = (const float*)d_in[10];
    const float* wcb        = (const float*)d_in[11];
    float* out = (float*)d_out;

    // 8 rows per block of 256 threads
    normE_kernel<<<(N_ENT + 7) / 8, 256>>>(E);
    prepRW_kernel<<<1, 64>>>(R, w1);
    hop1_kernel<<<BSZ, 64>>>(entity_idx, adj_e, adj_r, w1, w2, w3,
                             wxw, wxb, wcw, wcb, out);
    hop2_kernel<<<BSZ, 256>>>(entity_idx, adj_e, adj_r, w1, w2, w3,
                              wxw, wxb, wcw, wcb, out);
}

// round 3
// speedup vs baseline: 6.4655x; 6.4655x over previous
#include <cuda_runtime.h>
#include <math.h>

#define N_ENT 100000
#define N_REL 64
#define E_DIM 64
#define KNB   32
#define BSZ   1024

// Device scratch (no allocation allowed)
__device__ float d_Enorm[(size_t)N_ENT * E_DIM];   // normalized entity table (25.6 MB)
__device__ float d_RW[N_REL * E_DIM];              // RW[rel][f] = sum_e Rnorm[rel][e] * w1r[f][e]

__device__ __forceinline__ float leaky(float x) { return x >= 0.f ? x : 0.2f * x; }

// ---------------------------------------------------------------------------
// K0a: normalize all entity rows into d_Enorm. 1 warp per row.
// ---------------------------------------------------------------------------
__global__ void normE_kernel(const float* __restrict__ E) {
    int warp = (blockIdx.x * blockDim.x + threadIdx.x) >> 5;
    int lane = threadIdx.x & 31;
    if (warp >= N_ENT) return;
    const float2* row = (const float2*)(E + (size_t)warp * E_DIM);
    float2 v = row[lane];
    float ss = v.x * v.x + v.y * v.y;
    #pragma unroll
    for (int o = 16; o > 0; o >>= 1) ss += __shfl_xor_sync(0xffffffffu, ss, o);
    float n = sqrtf(ss);
    float sc = (n > 1.0f) ? 1.0f / (n + 1e-7f) : 1.0f;
    float2* orow = (float2*)(d_Enorm + (size_t)warp * E_DIM);
    orow[lane] = make_float2(v.x * sc, v.y * sc);
}

// ---------------------------------------------------------------------------
// K0b: normalize R; RW[rel][f] = sum_e Rnorm[rel][e] * w1[f*128+64+e]
// One block of 256 threads; all loads coalesced, smem padded (conflict-free).
// ---------------------------------------------------------------------------
__global__ void __launch_bounds__(256) prepRW_kernel(const float* __restrict__ R,
                                                     const float* __restrict__ w1) {
    __shared__ float Rn[N_REL * E_DIM];       // 16 KB
    __shared__ float w1rT[E_DIM * 65];        // transposed, padded
    int tid = threadIdx.x, w = tid >> 5, lane = tid & 31;

    // normalize R: 8 warps x 8 rows, coalesced float2 per lane
    #pragma unroll
    for (int k = 0; k < 8; k++) {
        int row = w * 8 + k;
        float2 v = ((const float2*)(R + row * E_DIM))[lane];
        float ss = v.x * v.x + v.y * v.y;
        #pragma unroll
        for (int o = 16; o > 0; o >>= 1) ss += __shfl_xor_sync(0xffffffffu, ss, o);
        float n = sqrtf(ss);
        float sc = (n > 1.0f) ? 1.0f / (n + 1e-7f) : 1.0f;
        Rn[row * E_DIM + lane * 2]     = v.x * sc;
        Rn[row * E_DIM + lane * 2 + 1] = v.y * sc;
    }
    // load w1r transposed: w1rT[e*65+f] = w1[f*128+64+e]
    for (int i = tid; i < E_DIM * E_DIM; i += 256) {
        int f = i >> 6, e = i & 63;
        w1rT[e * 65 + f] = w1[f * 128 + 64 + e];
    }
    __syncthreads();
    // 4096 outputs / 256 threads = 16 each
    #pragma unroll
    for (int j = 0; j < 16; j++) {
        int i = tid + j * 256;
        int rel = i >> 6, f = i & 63;
        float s = 0.f;
        #pragma unroll
        for (int e = 0; e < E_DIM; e++) s += Rn[rel * E_DIM + e] * w1rT[e * 65 + f];
        d_RW[rel * E_DIM + f] = s;
    }
}

// ---------------------------------------------------------------------------
// Fused per-root kernel: hop-1 + hop-2 GAT. One block (256 threads) per root.
// Attention factored through the 64-entry relation score table for BOTH hops.
// ---------------------------------------------------------------------------
__global__ void __launch_bounds__(256) fused_kernel(
        const int* __restrict__ entity_idx,
        const int* __restrict__ adj_e,
        const int* __restrict__ adj_r,
        const float* __restrict__ w1,
        const float* __restrict__ w2,
        const float* __restrict__ w3,
        const float* __restrict__ wxw,
        const float* __restrict__ wxb,
        const float* __restrict__ wcw,
        const float* __restrict__ wcb,
        float* __restrict__ out) {
    int b = blockIdx.x;
    int tid = threadIdx.x, w = tid >> 5, lane = tid & 31;

    __shared__ float t1[KNB * E_DIM];          // 8 KB  hop-1 neighbor rows
    __shared__ float W2T[E_DIM * 65];          // 16.6 KB transposed+padded W2
    __shared__ int   idx2[KNB * KNB];          // 4 KB
    __shared__ unsigned char rel2[KNB * KNB];  // 1 KB
    __shared__ float part[16 * 68];            // 4.25 KB gather partials (padded)
    __shared__ float hidW[8][E_DIM];           // per-warp MLP scratch
    __shared__ float eaT[2][N_REL];            // relation score tables (hop1, hop2)
    __shared__ float hS[E_DIM], hsumS[E_DIM];
    __shared__ float hWh[E_DIM], hWs[E_DIM];
    __shared__ float aggS[E_DIM], vS[E_DIM];
    __shared__ int   ent1[KNB], rel1[KNB];
    __shared__ float red8[8];
    __shared__ float sS1, sS2;

    int eidx = entity_idx[b];
    // ---- Phase A: root-level loads ----
    if (tid < KNB) {
        ent1[tid] = adj_e[eidx * KNB + tid];
        rel1[tid] = adj_r[eidx * KNB + tid];
    }
    if (tid < E_DIM) hS[tid] = d_Enorm[(size_t)eidx * E_DIM + tid];
    for (int i = tid; i < E_DIM * E_DIM; i += 256)
        W2T[(i & 63) * 65 + (i >> 6)] = w2[i];   // W2T[f*65+o] = w2[o*64+f]
    __syncthreads();

    // ---- Phase B: stage hop-2 indices (long-latency, issue early) + t1 rows ----
    for (int i = tid; i < KNB * KNB; i += 256) {
        int e1 = ent1[i >> 5];
        idx2[i] = adj_e[e1 * KNB + (i & 31)];
        rel2[i] = (unsigned char)adj_r[e1 * KNB + (i & 31)];
    }
    for (int i = tid; i < KNB * E_DIM; i += 256) {
        int n = i >> 6, e = i & 63;
        t1[i] = d_Enorm[(size_t)ent1[n] * E_DIM + e];
    }
    __syncthreads();

    // ---- hsum ----
    if (tid < E_DIM) {
        float s = 0.f;
        #pragma unroll
        for (int n = 0; n < KNB; n++) s += t1[n * E_DIM + tid];
        hsumS[tid] = s;
    }
    __syncthreads();

    // ---- query projections: hWh[f] = h . w1h[f], hWs[f] = hsum . w1h[f]
    // 128 jobs over 8 warps, coalesced float2 row loads + shuffle reduce.
    #pragma unroll
    for (int k = 0; k < 16; k++) {
        int job = w * 16 + k;
        int f = job & 63;
        const float* q = (job < 64) ? hS : hsumS;
        float2 wv = ((const float2*)(w1 + f * 128))[lane];
        float p = wv.x * q[lane * 2] + wv.y * q[lane * 2 + 1];
        #pragma unroll
        for (int o = 16; o > 0; o >>= 1) p += __shfl_down_sync(0xffffffffu, p, o);
        if (lane == 0) { if (job < 64) hWh[f] = p; else hWs[f] = p; }
    }
    __syncthreads();

    // ---- relation score tables: 128 entries (2 tables x 64 rels), 16 per warp
    float w3a = w3[lane], w3b = w3[lane + 32];
    #pragma unroll
    for (int k = 0; k < 16; k++) {
        int entry = w * 16 + k;
        int tbl = entry >> 6, rel = entry & 63;
        const float* hw = tbl ? hWs : hWh;
        float x0 = hw[lane]      + d_RW[rel * E_DIM + lane];
        float x1 = hw[lane + 32] + d_RW[rel * E_DIM + lane + 32];
        hidW[w][lane]      = x0 > 0.f ? x0 : 0.f;
        hidW[w][lane + 32] = x1 > 0.f ? x1 : 0.f;
        __syncwarp();
        float g0 = 0.f, g1 = 0.f;
        #pragma unroll
        for (int f = 0; f < E_DIM; f++) {
            float hv = hidW[w][f];                     // broadcast
            g0 += W2T[f * 65 + lane]      * hv;        // conflict-free
            g1 += W2T[f * 65 + lane + 32] * hv;
        }
        g0 = g0 > 0.f ? g0 : 0.f;
        g1 = g1 > 0.f ? g1 : 0.f;
        float c = w3a * g0 + w3b * g1;
        #pragma unroll
        for (int o = 16; o > 0; o >>= 1) c += __shfl_down_sync(0xffffffffu, c, o);
        if (lane == 0) eaT[tbl][rel] = expf(1.f / (1.f + expf(-c)));
        __syncwarp();
    }
    __syncthreads();

    // ---- hop-2 weighted gather FIRST (long pole; L2 latency covered by MLP=8)
    {
        const float4* E4 = (const float4*)d_Enorm;
        int seg = tid & 15, r = tid >> 4;
        float4 acc = make_float4(0.f, 0.f, 0.f, 0.f);
        #pragma unroll
        for (int base = 0; base < KNB * KNB; base += 128) {
            int   ids[8];
            float eas[8];
            float4 vs[8];
            #pragma unroll
            for (int u = 0; u < 8; u++) {
                int n = base + u * 16 + r;
                ids[u] = idx2[n];
                eas[u] = eaT[1][rel2[n]];
            }
            #pragma unroll
            for (int u = 0; u < 8; u++)
                vs[u] = __ldg(&E4[(size_t)ids[u] * 16 + seg]);
            #pragma unroll
            for (int u = 0; u < 8; u++) {
                acc.x += eas[u] * vs[u].x; acc.y += eas[u] * vs[u].y;
                acc.z += eas[u] * vs[u].z; acc.w += eas[u] * vs[u].w;
            }
        }
        ((float4*)(part + r * 68))[seg] = acc;
    }
    // S2 = sum of 1024 weights: each thread sums 4, warp reduce
    {
        float sp = 0.f;
        #pragma unroll
        for (int j = 0; j < 4; j++) sp += eaT[1][rel2[tid * 4 + j]];
        #pragma unroll
        for (int o = 16; o > 0; o >>= 1) sp += __shfl_down_sync(0xffffffffu, sp, o);
        if (lane == 0) red8[w] = sp;
    }
    __syncthreads();
    if (tid == 0) {
        float s = 0.f;
        #pragma unroll
        for (int i = 0; i < 8; i++) s += red8[i];
        sS2 = s;
    }

    // ---- hop-1 aggregation (t1 resident in smem) ----
    if (tid < E_DIM) {
        float ag = 0.f;
        #pragma unroll
        for (int n = 0; n < KNB; n++) ag += eaT[0][rel1[n]] * t1[n * E_DIM + tid];
        aggS[tid] = ag;
    }
    if (tid >= 64 && tid < 96) {
        int l2 = tid - 64;
        float e = eaT[0][rel1[l2]];
        #pragma unroll
        for (int o = 16; o > 0; o >>= 1) e += __shfl_down_sync(0xffffffffu, e, o);
        if (l2 == 0) sS1 = e;
    }
    __syncthreads();
    if (tid < E_DIM) aggS[tid] /= sS1;
    __syncthreads();

    // ---- hop-1 epilogue: v1 = leaky(wxw @ agg + b); emb1 = leaky(wcw @ [h,v1] + b)
    #pragma unroll
    for (int k = 0; k < 8; k++) {
        int o = w * 8 + k;
        float2 wv = ((const float2*)(wxw + o * E_DIM))[lane];
        float p = wv.x * aggS[lane * 2] + wv.y * aggS[lane * 2 + 1];
        #pragma unroll
        for (int off = 16; off > 0; off >>= 1) p += __shfl_down_sync(0xffffffffu, p, off);
        if (lane == 0) vS[o] = leaky(p + wxb[o]);
    }
    __syncthreads();
    #pragma unroll
    for (int k = 0; k < 8; k++) {
        int o = w * 8 + k;
        float4 wv = ((const float4*)(wcw + o * 128))[lane];
        int i0 = lane * 4;
        float x0 = (i0 < 64)     ? hS[i0]     : vS[i0 - 64];
        float x1 = (i0 + 1 < 64) ? hS[i0 + 1] : vS[i0 - 63];
        float x2 = (i0 + 2 < 64) ? hS[i0 + 2] : vS[i0 - 62];
        float x3 = (i0 + 3 < 64) ? hS[i0 + 3] : vS[i0 - 61];
        float p = wv.x * x0 + wv.y * x1 + wv.z * x2 + wv.w * x3;
        #pragma unroll
        for (int off = 16; off > 0; off >>= 1) p += __shfl_down_sync(0xffffffffu, p, off);
        if (lane == 0) out[b * 192 + 64 + o] = leaky(p + wcb[o]);
    }
    if (tid < E_DIM) out[b * 192 + 128 + tid] = hS[tid];
    __syncthreads();

    // ---- reduce gather partials, hop-2 epilogue ----
    if (tid < E_DIM) {
        float s = 0.f;
        #pragma unroll
        for (int r = 0; r < 16; r++) s += part[r * 68 + tid];
        aggS[tid] = s / sS2;
    }
    __syncthreads();
    #pragma unroll
    for (int k = 0; k < 8; k++) {
        int o = w * 8 + k;
        float2 wv = ((const float2*)(wxw + o * E_DIM))[lane];
        float p = wv.x * aggS[lane * 2] + wv.y * aggS[lane * 2 + 1];
        #pragma unroll
        for (int off = 16; off > 0; off >>= 1) p += __shfl_down_sync(0xffffffffu, p, off);
        if (lane == 0) vS[o] = leaky(p + wxb[o]);
    }
    __syncthreads();
    #pragma unroll
    for (int k = 0; k < 8; k++) {
        int o = w * 8 + k;
        float4 wv = ((const float4*)(wcw + o * 128))[lane];
        int i0 = lane * 4;
        float x0 = (i0 < 64)     ? hsumS[i0]     : vS[i0 - 64];
        float x1 = (i0 + 1 < 64) ? hsumS[i0 + 1] : vS[i0 - 63];
        float x2 = (i0 + 2 < 64) ? hsumS[i0 + 2] : vS[i0 - 62];
        float x3 = (i0 + 3 < 64) ? hsumS[i0 + 3] : vS[i0 - 61];
        float p = wv.x * x0 + wv.y * x1 + wv.z * x2 + wv.w * x3;
        #pragma unroll
        for (int off = 16; off > 0; off >>= 1) p += __shfl_down_sync(0xffffffffu, p, off);
        if (lane == 0) out[b * 192 + o] = leaky(p + wcb[o]);
    }
}

// ---------------------------------------------------------------------------
extern "C" void kernel_launch(void* const* d_in, const int* in_sizes, int n_in,
                              void* d_out, int out_size) {
    const int*   entity_idx = (const int*)d_in[0];
    const int*   adj_e      = (const int*)d_in[1];
    const int*   adj_r      = (const int*)d_in[2];
    const float* E          = (const float*)d_in[3];
    const float* R          = (const float*)d_in[4];
    const float* w1         = (const float*)d_in[5];
    const float* w2         = (const float*)d_in[6];
    const float* w3         = (const float*)d_in[7];
    const float* wxw        = (const float*)d_in[8];
    const float* wxb        = (const float*)d_in[9];
    const float* wcw        = (const float*)d_in[10];
    const float* wcb        = (const float*)d_in[11];
    float* out = (float*)d_out;

    normE_kernel<<<(N_ENT + 7) / 8, 256>>>(E);
    prepRW_kernel<<<1, 256>>>(R, w1);
    fused_kernel<<<BSZ, 256>>>(entity_idx, adj_e, adj_r, w1, w2, w3,
                               wxw, wxb, wcw, wcb, out);
}

// round 4
// speedup vs baseline: 7.3664x; 1.1393x over previous
#include <cuda_runtime.h>
#include <math.h>

#define N_ENT 100000
#define N_REL 64
#define E_DIM 64
#define KNB   32
#define BSZ   1024

typedef unsigned long long ull;

// Device scratch (no allocation allowed)
__device__ float d_Enorm[(size_t)N_ENT * E_DIM];   // normalized entity table (25.6 MB)
__device__ float d_RW[N_REL * E_DIM];              // RW[rel][f] = sum_e Rnorm[rel][e] * w1r[f][e]

__device__ __forceinline__ float leaky(float x) { return x >= 0.f ? x : 0.2f * x; }

__device__ __forceinline__ ull ffma2(ull a, ull b, ull c) {
    ull d;
    asm("fma.rn.f32x2 %0, %1, %2, %3;" : "=l"(d) : "l"(a), "l"(b), "l"(c));
    return d;
}

// ---------------------------------------------------------------------------
// K0a: normalize all entity rows. Half-warp (16 lanes, float4) per row.
// ---------------------------------------------------------------------------
__global__ void normE_kernel(const float* __restrict__ E) {
    int hw = (blockIdx.x * blockDim.x + threadIdx.x) >> 4;
    int l = threadIdx.x & 15;
    if (hw >= N_ENT) return;
    const float4* row = (const float4*)(E + (size_t)hw * E_DIM);
    float4 v = row[l];
    float ss = v.x * v.x + v.y * v.y + v.z * v.z + v.w * v.w;
    #pragma unroll
    for (int o = 8; o > 0; o >>= 1) ss += __shfl_xor_sync(0xffffffffu, ss, o);
    float n = sqrtf(ss);
    float sc = (n > 1.0f) ? 1.0f / (n + 1e-7f) : 1.0f;
    float4* orow = (float4*)(d_Enorm + (size_t)hw * E_DIM);
    orow[l] = make_float4(v.x * sc, v.y * sc, v.z * sc, v.w * sc);
}

// ---------------------------------------------------------------------------
// K0b: normalize R; RW[rel][f] = sum_e Rnorm[rel][e] * w1[f*128+64+e]
// ---------------------------------------------------------------------------
__global__ void __launch_bounds__(256) prepRW_kernel(const float* __restrict__ R,
                                                     const float* __restrict__ w1) {
    __shared__ float Rn[N_REL * E_DIM];       // 16 KB
    __shared__ float w1rT[E_DIM * 65];        // transposed, padded
    int tid = threadIdx.x, w = tid >> 5, lane = tid & 31;

    #pragma unroll
    for (int k = 0; k < 8; k++) {
        int row = w * 8 + k;
        float2 v = ((const float2*)(R + row * E_DIM))[lane];
        float ss = v.x * v.x + v.y * v.y;
        #pragma unroll
        for (int o = 16; o > 0; o >>= 1) ss += __shfl_xor_sync(0xffffffffu, ss, o);
        float n = sqrtf(ss);
        float sc = (n > 1.0f) ? 1.0f / (n + 1e-7f) : 1.0f;
        Rn[row * E_DIM + lane * 2]     = v.x * sc;
        Rn[row * E_DIM + lane * 2 + 1] = v.y * sc;
    }
    for (int i = tid; i < E_DIM * E_DIM; i += 256) {
        int f = i >> 6, e = i & 63;
        w1rT[e * 65 + f] = w1[f * 128 + 64 + e];
    }
    __syncthreads();
    #pragma unroll
    for (int j = 0; j < 16; j++) {
        int i = tid + j * 256;
        int rel = i >> 6, f = i & 63;
        float s = 0.f;
        #pragma unroll
        for (int e = 0; e < E_DIM; e++) s += Rn[rel * E_DIM + e] * w1rT[e * 65 + f];
        d_RW[rel * E_DIM + f] = s;
    }
}

// ---------------------------------------------------------------------------
// Fused per-root kernel. One block (256 threads) per root.
// Score MLP: 96 entries (32 hop-1 per-neighbor + 64 hop-2 per-rel),
// 2 entries per warp pair-batched with FFMA2 (f32x2) packed math.
// ---------------------------------------------------------------------------
__global__ void __launch_bounds__(256) fused_kernel(
        const int* __restrict__ entity_idx,
        const int* __restrict__ adj_e,
        const int* __restrict__ adj_r,
        const float* __restrict__ w1,
        const float* __restrict__ w2,
        const float* __restrict__ w3,
        const float* __restrict__ wxw,
        const float* __restrict__ wxb,
        const float* __restrict__ wcw,
        const float* __restrict__ wcb,
        float* __restrict__ out) {
    int b = blockIdx.x;
    int tid = threadIdx.x, w = tid >> 5, lane = tid & 31;

    __shared__ float  t1[KNB * E_DIM];          // 8 KB
    __shared__ float2 W2P[E_DIM * 32];          // 16 KB: W2P[f*32+o] = (w2[o][f], w2[o+32][f])
    __shared__ int    idx2[KNB * KNB];          // 4 KB
    __shared__ unsigned char rel2[KNB * KNB];   // 1 KB
    __shared__ float  part[16 * 68];            // 4.25 KB
    __shared__ float2 hidP[8][2][E_DIM];        // 8 KB per-warp duplicated hid pairs
    __shared__ float  ea1[KNB];                 // hop-1 per-neighbor exp(score)
    __shared__ float  eaT2[N_REL];              // hop-2 per-rel exp(score)
    __shared__ float  hS[E_DIM], hsumS[E_DIM];
    __shared__ float  hWh[E_DIM], hWs[E_DIM];
    __shared__ float  aggS[E_DIM], vS[E_DIM];
    __shared__ int    ent1[KNB], rel1[KNB];
    __shared__ float  red8[8];
    __shared__ float  sS1, sS2;

    int eidx = entity_idx[b];
    // ---- Phase A ----
    if (tid < KNB) {
        ent1[tid] = adj_e[eidx * KNB + tid];
        rel1[tid] = adj_r[eidx * KNB + tid];
    }
    if (tid < E_DIM) hS[tid] = d_Enorm[(size_t)eidx * E_DIM + tid];
    for (int i = tid; i < E_DIM * E_DIM; i += 256) {
        int o = i >> 6, f = i & 63;
        if (o < 32) W2P[f * 32 + o].x = w2[i];
        else        W2P[f * 32 + (o - 32)].y = w2[i];
    }
    __syncthreads();

    // ---- Phase B: stage hop-2 indices + t1 rows ----
    for (int i = tid; i < KNB * KNB; i += 256) {
        int e1 = ent1[i >> 5];
        idx2[i] = adj_e[e1 * KNB + (i & 31)];
        rel2[i] = (unsigned char)adj_r[e1 * KNB + (i & 31)];
    }
    for (int i = tid; i < KNB * E_DIM; i += 256) {
        int n = i >> 6, e = i & 63;
        t1[i] = d_Enorm[(size_t)ent1[n] * E_DIM + e];
    }
    __syncthreads();

    // ---- hsum ----
    if (tid < E_DIM) {
        float s = 0.f;
        #pragma unroll
        for (int n = 0; n < KNB; n++) s += t1[n * E_DIM + tid];
        hsumS[tid] = s;
    }
    __syncthreads();

    // ---- query projections ----
    #pragma unroll
    for (int k = 0; k < 16; k++) {
        int job = w * 16 + k;
        int f = job & 63;
        const float* q = (job < 64) ? hS : hsumS;
        float2 wv = ((const float2*)(w1 + f * 128))[lane];
        float p = wv.x * q[lane * 2] + wv.y * q[lane * 2 + 1];
        #pragma unroll
        for (int o = 16; o > 0; o >>= 1) p += __shfl_down_sync(0xffffffffu, p, o);
        if (lane == 0) { if (job < 64) hWh[f] = p; else hWs[f] = p; }
    }
    __syncthreads();

    // ---- score tables: 96 entries, 12 per warp, pair-batched, FFMA2 ----
    {
        float w3a = w3[lane], w3b = w3[lane + 32];
        const ull* W2u = (const ull*)W2P;
        const ull* h0u = (const ull*)hidP[w][0];
        const ull* h1u = (const ull*)hidP[w][1];
        #pragma unroll
        for (int pr = 0; pr < 6; pr++) {
            int e0 = w * 12 + pr * 2;
            #pragma unroll
            for (int j = 0; j < 2; j++) {
                int entry = e0 + j;
                int isH2 = entry >= KNB;
                int rel = isH2 ? (entry - KNB) : rel1[entry];
                const float* hw = isH2 ? hWs : hWh;
                float x0 = hw[lane]      + d_RW[rel * E_DIM + lane];
                float x1 = hw[lane + 32] + d_RW[rel * E_DIM + lane + 32];
                x0 = x0 > 0.f ? x0 : 0.f;
                x1 = x1 > 0.f ? x1 : 0.f;
                hidP[w][j][lane]      = make_float2(x0, x0);
                hidP[w][j][lane + 32] = make_float2(x1, x1);
            }
            __syncwarp();
            ull acc0 = 0ull, acc1 = 0ull;
            #pragma unroll
            for (int f = 0; f < E_DIM; f++) {
                ull wp = W2u[f * 32 + lane];
                acc0 = ffma2(wp, h0u[f], acc0);
                acc1 = ffma2(wp, h1u[f], acc1);
            }
            #pragma unroll
            for (int j = 0; j < 2; j++) {
                ull a = j ? acc1 : acc0;
                float g0 = __uint_as_float((unsigned)(a & 0xffffffffull));
                float g1 = __uint_as_float((unsigned)(a >> 32));
                g0 = g0 > 0.f ? g0 : 0.f;
                g1 = g1 > 0.f ? g1 : 0.f;
                float c = w3a * g0 + w3b * g1;
                #pragma unroll
                for (int o = 16; o > 0; o >>= 1) c += __shfl_down_sync(0xffffffffu, c, o);
                if (lane == 0) {
                    int entry = e0 + j;
                    float ev = expf(1.f / (1.f + expf(-c)));
                    if (entry < KNB) ea1[entry] = ev;
                    else             eaT2[entry - KNB] = ev;
                }
            }
            __syncwarp();
        }
    }
    __syncthreads();

    // ---- hop-2 weighted gather (MLP=8 batched float4 loads) ----
    {
        const float4* E4 = (const float4*)d_Enorm;
        int seg = tid & 15, r = tid >> 4;
        float4 acc = make_float4(0.f, 0.f, 0.f, 0.f);
        #pragma unroll
        for (int base = 0; base < KNB * KNB; base += 128) {
            int   ids[8];
            float eas[8];
            float4 vs[8];
            #pragma unroll
            for (int u = 0; u < 8; u++) {
                int n = base + u * 16 + r;
                ids[u] = idx2[n];
                eas[u] = eaT2[rel2[n]];
            }
            #pragma unroll
            for (int u = 0; u < 8; u++)
                vs[u] = __ldg(&E4[(size_t)ids[u] * 16 + seg]);
            #pragma unroll
            for (int u = 0; u < 8; u++) {
                acc.x += eas[u] * vs[u].x; acc.y += eas[u] * vs[u].y;
                acc.z += eas[u] * vs[u].z; acc.w += eas[u] * vs[u].w;
            }
        }
        ((float4*)(part + r * 68))[seg] = acc;
    }
    // S2 = sum of 1024 weights
    {
        float sp = 0.f;
        #pragma unroll
        for (int j = 0; j < 4; j++) sp += eaT2[rel2[tid * 4 + j]];
        #pragma unroll
        for (int o = 16; o > 0; o >>= 1) sp += __shfl_down_sync(0xffffffffu, sp, o);
        if (lane == 0) red8[w] = sp;
    }
    __syncthreads();
    if (tid == 0) {
        float s = 0.f;
        #pragma unroll
        for (int i = 0; i < 8; i++) s += red8[i];
        sS2 = s;
    }

    // ---- hop-1 aggregation ----
    if (tid < E_DIM) {
        float ag = 0.f;
        #pragma unroll
        for (int n = 0; n < KNB; n++) ag += ea1[n] * t1[n * E_DIM + tid];
        aggS[tid] = ag;
    }
    if (tid >= 64 && tid < 96) {
        int l2 = tid - 64;
        float e = ea1[l2];
        #pragma unroll
        for (int o = 16; o > 0; o >>= 1) e += __shfl_down_sync(0xffffffffu, e, o);
        if (l2 == 0) sS1 = e;
    }
    __syncthreads();
    if (tid < E_DIM) aggS[tid] /= sS1;
    __syncthreads();

    // ---- hop-1 epilogue ----
    #pragma unroll
    for (int k = 0; k < 8; k++) {
        int o = w * 8 + k;
        float2 wv = ((const float2*)(wxw + o * E_DIM))[lane];
        float p = wv.x * aggS[lane * 2] + wv.y * aggS[lane * 2 + 1];
        #pragma unroll
        for (int off = 16; off > 0; off >>= 1) p += __shfl_down_sync(0xffffffffu, p, off);
        if (lane == 0) vS[o] = leaky(p + wxb[o]);
    }
    __syncthreads();
    #pragma unroll
    for (int k = 0; k < 8; k++) {
        int o = w * 8 + k;
        float4 wv = ((const float4*)(wcw + o * 128))[lane];
        int i0 = lane * 4;
        float x0 = (i0 < 64)     ? hS[i0]     : vS[i0 - 64];
        float x1 = (i0 + 1 < 64) ? hS[i0 + 1] : vS[i0 - 63];
        float x2 = (i0 + 2 < 64) ? hS[i0 + 2] : vS[i0 - 62];
        float x3 = (i0 + 3 < 64) ? hS[i0 + 3] : vS[i0 - 61];
        float p = wv.x * x0 + wv.y * x1 + wv.z * x2 + wv.w * x3;
        #pragma unroll
        for (int off = 16; off > 0; off >>= 1) p += __shfl_down_sync(0xffffffffu, p, off);
        if (lane == 0) out[b * 192 + 64 + o] = leaky(p + wcb[o]);
    }
    if (tid < E_DIM) out[b * 192 + 128 + tid] = hS[tid];
    __syncthreads();

    // ---- hop-2 epilogue ----
    if (tid < E_DIM) {
        float s = 0.f;
        #pragma unroll
        for (int r = 0; r < 16; r++) s += part[r * 68 + tid];
        aggS[tid] = s / sS2;
    }
    __syncthreads();
    #pragma unroll
    for (int k = 0; k < 8; k++) {
        int o = w * 8 + k;
        float2 wv = ((const float2*)(wxw + o * E_DIM))[lane];
        float p = wv.x * aggS[lane * 2] + wv.y * aggS[lane * 2 + 1];
        #pragma unroll
        for (int off = 16; off > 0; off >>= 1) p += __shfl_down_sync(0xffffffffu, p, off);
        if (lane == 0) vS[o] = leaky(p + wxb[o]);
    }
    __syncthreads();
    #pragma unroll
    for (int k = 0; k < 8; k++) {
        int o = w * 8 + k;
        float4 wv = ((const float4*)(wcw + o * 128))[lane];
        int i0 = lane * 4;
        float x0 = (i0 < 64)     ? hsumS[i0]     : vS[i0 - 64];
        float x1 = (i0 + 1 < 64) ? hsumS[i0 + 1] : vS[i0 - 63];
        float x2 = (i0 + 2 < 64) ? hsumS[i0 + 2] : vS[i0 - 62];
        float x3 = (i0 + 3 < 64) ? hsumS[i0 + 3] : vS[i0 - 61];
        float p = wv.x * x0 + wv.y * x1 + wv.z * x2 + wv.w * x3;
        #pragma unroll
        for (int off = 16; off > 0; off >>= 1) p += __shfl_down_sync(0xffffffffu, p, off);
        if (lane == 0) out[b * 192 + o] = leaky(p + wcb[o]);
    }
}

// ---------------------------------------------------------------------------
extern "C" void kernel_launch(void* const* d_in, const int* in_sizes, int n_in,
                              void* d_out, int out_size) {
    const int*   entity_idx = (const int*)d_in[0];
    const int*   adj_e      = (const int*)d_in[1];
    const int*   adj_r      = (const int*)d_in[2];
    const float* E          = (const float*)d_in[3];
    const float* R          = (const float*)d_in[4];
    const float* w1         = (const float*)d_in[5];
    const float* w2         = (const float*)d_in[6];
    const float* w3         = (const float*)d_in[7];
    const float* wxw        = (const float*)d_in[8];
    const float* wxb        = (const float*)d_in[9];
    const float* wcw        = (const float*)d_in[10];
    const float* wcb        = (const float*)d_in[11];
    float* out = (float*)d_out;

    normE_kernel<<<(N_ENT * 16 + 255) / 256, 256>>>(E);
    prepRW_kernel<<<1, 256>>>(R, w1);
    fused_kernel<<<BSZ, 256>>>(entity_idx, adj_e, adj_r, w1, w2, w3,
                               wxw, wxb, wcw, wcb, out);
}

// round 5
// speedup vs baseline: 8.9042x; 1.2087x over previous
#include <cuda_runtime.h>
#include <math.h>

#define N_ENT 100000
#define N_REL 64
#define E_DIM 64
#define KNB   32
#define BSZ   1024

typedef unsigned long long ull;

// Device scratch (no allocation allowed)
__device__ float  d_scale[N_ENT];            // per-entity normalization scale
__device__ float  d_RW[N_REL * E_DIM];       // RW[rel][f] = Rnorm[rel] . w1r[f]
__device__ float2 d_W2P[E_DIM * 32];         // d_W2P[f*32+q] = (w2[q][f], w2[q+32][f])

__device__ __forceinline__ float leaky(float x) { return x >= 0.f ? x : 0.2f * x; }

__device__ __forceinline__ ull ffma2(ull a, ull b, ull c) {
    ull d;
    asm("fma.rn.f32x2 %0, %1, %2, %3;" : "=l"(d) : "l"(a), "l"(b), "l"(c));
    return d;
}
__device__ __forceinline__ ull packdup(float x) {
    ull d;
    asm("mov.b64 %0, {%1, %1};" : "=l"(d) : "f"(x));
    return d;
}

// ---------------------------------------------------------------------------
// K0a: per-entity norm scale. Half-warp (16 lanes, float4) per row.
// ---------------------------------------------------------------------------
__global__ void normScale_kernel(const float* __restrict__ E) {
    int hw = (blockIdx.x * blockDim.x + threadIdx.x) >> 4;
    int l = threadIdx.x & 15;
    if (hw >= N_ENT) return;
    float4 v = ((const float4*)(E + (size_t)hw * E_DIM))[l];
    float ss = v.x * v.x + v.y * v.y + v.z * v.z + v.w * v.w;
    #pragma unroll
    for (int o = 8; o > 0; o >>= 1) ss += __shfl_xor_sync(0xffffffffu, ss, o);
    if (l == 0) {
        float n = sqrtf(ss);
        d_scale[hw] = (n > 1.0f) ? 1.0f / (n + 1e-7f) : 1.0f;
    }
}

// ---------------------------------------------------------------------------
// K0b: normalize R; RW[rel][f]; pre-pair W2 into d_W2P.
// ---------------------------------------------------------------------------
__global__ void __launch_bounds__(256) prepRW_kernel(const float* __restrict__ R,
                                                     const float* __restrict__ w1,
                                                     const float* __restrict__ w2) {
    __shared__ float Rn[N_REL * E_DIM];       // 16 KB
    __shared__ float w1rT[E_DIM * 65];        // transposed, padded
    int tid = threadIdx.x, w = tid >> 5, lane = tid & 31;

    #pragma unroll
    for (int k = 0; k < 8; k++) {
        int row = w * 8 + k;
        float2 v = ((const float2*)(R + row * E_DIM))[lane];
        float ss = v.x * v.x + v.y * v.y;
        #pragma unroll
        for (int o = 16; o > 0; o >>= 1) ss += __shfl_xor_sync(0xffffffffu, ss, o);
        float n = sqrtf(ss);
        float sc = (n > 1.0f) ? 1.0f / (n + 1e-7f) : 1.0f;
        Rn[row * E_DIM + lane * 2]     = v.x * sc;
        Rn[row * E_DIM + lane * 2 + 1] = v.y * sc;
    }
    for (int i = tid; i < E_DIM * E_DIM; i += 256) {
        int f = i >> 6, e = i & 63;
        w1rT[e * 65 + f] = w1[f * 128 + 64 + e];
    }
    // pre-pair W2 (one-time): d_W2P[f*32+q] = (w2[q][f], w2[q+32][f])
    #pragma unroll
    for (int j = 0; j < 8; j++) {
        int i = tid + j * 256;               // i = f*32+q
        int f = i >> 5, q = i & 31;
        d_W2P[i] = make_float2(w2[q * E_DIM + f], w2[(q + 32) * E_DIM + f]);
    }
    __syncthreads();
    #pragma unroll
    for (int j = 0; j < 16; j++) {
        int i = tid + j * 256;
        int rel = i >> 6, f = i & 63;
        float s = 0.f;
        #pragma unroll
        for (int e = 0; e < E_DIM; e++) s += Rn[rel * E_DIM + e] * w1rT[e * 65 + f];
        d_RW[rel * E_DIM + f] = s;
    }
}

// ---------------------------------------------------------------------------
// Fused per-root kernel. One block (256 threads) per root.
// Score MLP as output-stationary register GEMM:
//   thread (w,lane) owns o-pairs {w*4..w*4+3} x entries {lane*3..lane*3+2},
//   12 packed f32x2 accumulators, W2 via broadcast LDG.64 from d_W2P,
//   hid via conflict-free LDS.32 from bank-padded hidAll.
// Entries: 0..31 = hop-1 neighbors (query hWh), 32..95 = hop-2 rels (query hWs).
// ---------------------------------------------------------------------------
__global__ void __launch_bounds__(256) fused_kernel(
        const int* __restrict__ entity_idx,
        const int* __restrict__ adj_e,
        const int* __restrict__ adj_r,
        const float* __restrict__ E,
        const float* __restrict__ w1,
        const float* __restrict__ w3,
        const float* __restrict__ wxw,
        const float* __restrict__ wxb,
        const float* __restrict__ wcw,
        const float* __restrict__ wcb,
        float* __restrict__ out) {
    int b = blockIdx.x;
    int tid = threadIdx.x, w = tid >> 5, lane = tid & 31;

    __shared__ float  t1[KNB * E_DIM];          // 8 KB (normalized hop-1 rows)
    __shared__ int    idx2[KNB * KNB];          // 4 KB
    __shared__ unsigned char rel2[KNB * KNB];   // 1 KB
    __shared__ float  hidAll[32 * 97];          // 12.1 KB (also reused as gather partials)
    __shared__ float  scoreP[8][96];            // 3 KB per-warp score partials
    __shared__ float  eaAll[96];                // exp(sigmoid(score)) per entry
    __shared__ float  hS[E_DIM], hsumS[E_DIM];
    __shared__ float  hWh[E_DIM], hWs[E_DIM];
    __shared__ float  aggS[E_DIM], vS[E_DIM];
    __shared__ int    ent1[KNB], rel1[KNB];
    __shared__ float  red8[8];
    __shared__ float  sS1, sS2;

    float* part = hidAll;                       // union: gather partials (16*68 <= 32*97)

    int eidx = entity_idx[b];
    // ---- Phase A: root loads ----
    if (tid < KNB) {
        ent1[tid] = adj_e[eidx * KNB + tid];
        rel1[tid] = adj_r[eidx * KNB + tid];
    }
    if (tid < E_DIM) hS[tid] = E[(size_t)eidx * E_DIM + tid] * __ldg(&d_scale[eidx]);
    __syncthreads();

    // ---- Phase B: hop-2 indices + normalized t1 rows ----
    for (int i = tid; i < KNB * KNB; i += 256) {
        int e1 = ent1[i >> 5];
        idx2[i] = adj_e[e1 * KNB + (i & 31)];
        rel2[i] = (unsigned char)adj_r[e1 * KNB + (i & 31)];
    }
    for (int i = tid; i < KNB * E_DIM; i += 256) {
        int n = i >> 6, e = i & 63;
        int id = ent1[n];
        t1[i] = E[(size_t)id * E_DIM + e] * __ldg(&d_scale[id]);
    }
    __syncthreads();

    // ---- hsum ----
    if (tid < E_DIM) {
        float s = 0.f;
        #pragma unroll
        for (int n = 0; n < KNB; n++) s += t1[n * E_DIM + tid];
        hsumS[tid] = s;
    }
    __syncthreads();

    // ---- query projections: hWh[f] = h.w1h[f], hWs[f] = hsum.w1h[f] ----
    #pragma unroll
    for (int k = 0; k < 16; k++) {
        int job = w * 16 + k;
        int f = job & 63;
        const float* q = (job < 64) ? hS : hsumS;
        float2 wv = ((const float2*)(w1 + f * 128))[lane];
        float p = wv.x * q[lane * 2] + wv.y * q[lane * 2 + 1];
        #pragma unroll
        for (int o = 16; o > 0; o >>= 1) p += __shfl_down_sync(0xffffffffu, p, o);
        if (lane == 0) { if (job < 64) hWh[f] = p; else hWs[f] = p; }
    }
    __syncthreads();

    // ---- score GEMM: 2 passes of 32 f-steps each ----
    ull acc[4][3];
    #pragma unroll
    for (int q = 0; q < 4; q++)
        #pragma unroll
        for (int j = 0; j < 3; j++) acc[q][j] = 0ull;

    const ull* W2u = (const ull*)d_W2P;
    int e0 = lane * 3;
    #pragma unroll
    for (int p = 0; p < 2; p++) {
        // build hidAll[fl*97+entry] = relu(q[f] + RW[rel][f]) for f in [p*32, p*32+32)
        if (tid < 192) {
            int entry = tid >> 1, fh = tid & 1;
            int rel = (entry < KNB) ? rel1[entry] : (entry - KNB);
            const float* qv = (entry < KNB) ? hWh : hWs;
            #pragma unroll
            for (int j = 0; j < 16; j++) {
                int fl = fh * 16 + j;
                int f = p * 32 + fl;
                float x = qv[f] + __ldg(&d_RW[rel * E_DIM + f]);
                hidAll[fl * 97 + entry] = x > 0.f ? x : 0.f;
            }
        }
        __syncthreads();
        // accumulate
        #pragma unroll
        for (int fl = 0; fl < 32; fl++) {
            int f = p * 32 + fl;
            ull w0 = __ldg(&W2u[f * 32 + w * 4 + 0]);
            ull w1v = __ldg(&W2u[f * 32 + w * 4 + 1]);
            ull w2v = __ldg(&W2u[f * 32 + w * 4 + 2]);
            ull w3v = __ldg(&W2u[f * 32 + w * 4 + 3]);
            ull h0 = packdup(hidAll[fl * 97 + e0]);
            ull h1 = packdup(hidAll[fl * 97 + e0 + 1]);
            ull h2 = packdup(hidAll[fl * 97 + e0 + 2]);
            acc[0][0] = ffma2(w0, h0, acc[0][0]);
            acc[0][1] = ffma2(w0, h1, acc[0][1]);
            acc[0][2] = ffma2(w0, h2, acc[0][2]);
            acc[1][0] = ffma2(w1v, h0, acc[1][0]);
            acc[1][1] = ffma2(w1v, h1, acc[1][1]);
            acc[1][2] = ffma2(w1v, h2, acc[1][2]);
            acc[2][0] = ffma2(w2v, h0, acc[2][0]);
            acc[2][1] = ffma2(w2v, h1, acc[2][1]);
            acc[2][2] = ffma2(w2v, h2, acc[2][2]);
            acc[3][0] = ffma2(w3v, h0, acc[3][0]);
            acc[3][1] = ffma2(w3v, h1, acc[3][1]);
            acc[3][2] = ffma2(w3v, h2, acc[3][2]);
        }
        __syncthreads();   // hidAll reused next pass / as part buffer
    }

    // ---- relu + w3 dot, per-warp partials, cross-warp reduce ----
    {
        float w3v[4], w3u[4];
        #pragma unroll
        for (int q = 0; q < 4; q++) {
            int o = w * 4 + q;
            w3v[q] = __ldg(&w3[o]);
            w3u[q] = __ldg(&w3[o + 32]);
        }
        #pragma unroll
        for (int j = 0; j < 3; j++) {
            float s = 0.f;
            #pragma unroll
            for (int q = 0; q < 4; q++) {
                ull a = acc[q][j];
                float g0 = __uint_as_float((unsigned)(a & 0xffffffffull));
                float g1 = __uint_as_float((unsigned)(a >> 32));
                g0 = g0 > 0.f ? g0 : 0.f;
                g1 = g1 > 0.f ? g1 : 0.f;
                s += w3v[q] * g0 + w3u[q] * g1;
            }
            scoreP[w][e0 + j] = s;
        }
    }
    __syncthreads();
    if (tid < 96) {
        float c = 0.f;
        #pragma unroll
        for (int ww = 0; ww < 8; ww++) c += scoreP[ww][tid];
        eaAll[tid] = expf(1.f / (1.f + expf(-c)));
    }
    __syncthreads();

    // ---- hop-2 weighted gather (weights folded with per-row scale) ----
    {
        const float4* E4 = (const float4*)E;
        int seg = tid & 15, r = tid >> 4;
        float4 gacc = make_float4(0.f, 0.f, 0.f, 0.f);
        #pragma unroll
        for (int base = 0; base < KNB * KNB; base += 128) {
            int   ids[8];
            float eas[8];
            float4 vs[8];
            #pragma unroll
            for (int u8 = 0; u8 < 8; u8++) {
                int n = base + u8 * 16 + r;
                ids[u8] = idx2[n];
                eas[u8] = eaAll[32 + rel2[n]];
            }
            #pragma unroll
            for (int u8 = 0; u8 < 8; u8++) {
                eas[u8] *= __ldg(&d_scale[ids[u8]]);
                vs[u8] = __ldg(&E4[(size_t)ids[u8] * 16 + seg]);
            }
            #pragma unroll
            for (int u8 = 0; u8 < 8; u8++) {
                gacc.x += eas[u8] * vs[u8].x; gacc.y += eas[u8] * vs[u8].y;
                gacc.z += eas[u8] * vs[u8].z; gacc.w += eas[u8] * vs[u8].w;
            }
        }
        ((float4*)(part + r * 68))[seg] = gacc;
    }
    // S2 = sum of 1024 softmax numerators (scale NOT included — it multiplies t)
    {
        float sp = 0.f;
        #pragma unroll
        for (int j = 0; j < 4; j++) sp += eaAll[32 + rel2[tid * 4 + j]];
        #pragma unroll
        for (int o = 16; o > 0; o >>= 1) sp += __shfl_down_sync(0xffffffffu, sp, o);
        if (lane == 0) red8[w] = sp;
    }
    __syncthreads();
    if (tid == 0) {
        float s = 0.f;
        #pragma unroll
        for (int i = 0; i < 8; i++) s += red8[i];
        sS2 = s;
    }

    // ---- hop-1 aggregation ----
    if (tid < E_DIM) {
        float ag = 0.f;
        #pragma unroll
        for (int n = 0; n < KNB; n++) ag += eaAll[n] * t1[n * E_DIM + tid];
        aggS[tid] = ag;
    }
    if (tid >= 64 && tid < 96) {
        int l2 = tid - 64;
        float e = eaAll[l2];
        #pragma unroll
        for (int o = 16; o > 0; o >>= 1) e += __shfl_down_sync(0xffffffffu, e, o);
        if (l2 == 0) sS1 = e;
    }
    __syncthreads();
    if (tid < E_DIM) aggS[tid] /= sS1;
    __syncthreads();

    // ---- hop-1 epilogue ----
    #pragma unroll
    for (int k = 0; k < 8; k++) {
        int o = w * 8 + k;
        float2 wv = ((const float2*)(wxw + o * E_DIM))[lane];
        float p = wv.x * aggS[lane * 2] + wv.y * aggS[lane * 2 + 1];
        #pragma unroll
        for (int off = 16; off > 0; off >>= 1) p += __shfl_down_sync(0xffffffffu, p, off);
        if (lane == 0) vS[o] = leaky(p + wxb[o]);
    }
    __syncthreads();
    #pragma unroll
    for (int k = 0; k < 8; k++) {
        int o = w * 8 + k;
        float4 wv = ((const float4*)(wcw + o * 128))[lane];
        int i0 = lane * 4;
        float x0 = (i0 < 64)     ? hS[i0]     : vS[i0 - 64];
        float x1 = (i0 + 1 < 64) ? hS[i0 + 1] : vS[i0 - 63];
        float x2 = (i0 + 2 < 64) ? hS[i0 + 2] : vS[i0 - 62];
        float x3 = (i0 + 3 < 64) ? hS[i0 + 3] : vS[i0 - 61];
        float p = wv.x * x0 + wv.y * x1 + wv.z * x2 + wv.w * x3;
        #pragma unroll
        for (int off = 16; off > 0; off >>= 1) p += __shfl_down_sync(0xffffffffu, p, off);
        if (lane == 0) out[b * 192 + 64 + o] = leaky(p + wcb[o]);
    }
    if (tid < E_DIM) out[b * 192 + 128 + tid] = hS[tid];
    __syncthreads();

    // ---- hop-2 epilogue ----
    if (tid < E_DIM) {
        float s = 0.f;
        #pragma unroll
        for (int r = 0; r < 16; r++) s += part[r * 68 + tid];
        aggS[tid] = s / sS2;
    }
    __syncthreads();
    #pragma unroll
    for (int k = 0; k < 8; k++) {
        int o = w * 8 + k;
        float2 wv = ((const float2*)(wxw + o * E_DIM))[lane];
        float p = wv.x * aggS[lane * 2] + wv.y * aggS[lane * 2 + 1];
        #pragma unroll
        for (int off = 16; off > 0; off >>= 1) p += __shfl_down_sync(0xffffffffu, p, off);
        if (lane == 0) vS[o] = leaky(p + wxb[o]);
    }
    __syncthreads();
    #pragma unroll
    for (int k = 0; k < 8; k++) {
        int o = w * 8 + k;
        float4 wv = ((const float4*)(wcw + o * 128))[lane];
        int i0 = lane * 4;
        float x0 = (i0 < 64)     ? hsumS[i0]     : vS[i0 - 64];
        float x1 = (i0 + 1 < 64) ? hsumS[i0 + 1] : vS[i0 - 63];
        float x2 = (i0 + 2 < 64) ? hsumS[i0 + 2] : vS[i0 - 62];
        float x3 = (i0 + 3 < 64) ? hsumS[i0 + 3] : vS[i0 - 61];
        float p = wv.x * x0 + wv.y * x1 + wv.z * x2 + wv.w * x3;
        #pragma unroll
        for (int off = 16; off > 0; off >>= 1) p += __shfl_down_sync(0xffffffffu, p, off);
        if (lane == 0) out[b * 192 + o] = leaky(p + wcb[o]);
    }
}

// ---------------------------------------------------------------------------
extern "C" void kernel_launch(void* const* d_in, const int* in_sizes, int n_in,
                              void* d_out, int out_size) {
    const int*   entity_idx = (const int*)d_in[0];
    const int*   adj_e      = (const int*)d_in[1];
    const int*   adj_r      = (const int*)d_in[2];
    const float* E          = (const float*)d_in[3];
    const float* R          = (const float*)d_in[4];
    const float* w1         = (const float*)d_in[5];
    const float* w2         = (const float*)d_in[6];
    const float* w3         = (const float*)d_in[7];
    const float* wxw        = (const float*)d_in[8];
    const float* wxb        = (const float*)d_in[9];
    const float* wcw        = (const float*)d_in[10];
    const float* wcb        = (const float*)d_in[11];
    float* out = (float*)d_out;

    normScale_kernel<<<(N_ENT * 16 + 255) / 256, 256>>>(E);
    prepRW_kernel<<<1, 256>>>(R, w1, w2);
    fused_kernel<<<BSZ, 256>>>(entity_idx, adj_e, adj_r, E, w1, w3,
                               wxw, wxb, wcw, wcb, out);
}